// round 4
// baseline (speedup 1.0000x reference)
#include <cuda_runtime.h>

// Problem constants
#define NC 52
#define NR 4
#define NT 16
#define NS 128
#define NRAYS 64
#define RT (NR*NT)                 // 64 contiguous (r,t) per (ray,s,ch)
#define X_S_STRIDE (3*NC*RT)       // 9984 floats per s-step in x
#define Z_S_STRIDE (2*NC*RT)       // 6656 floats per s-step in z_vals
#define N_ELEMS (NRAYS*NC*RT)      // 212,992 complex outputs

// One thread per output channel (ray, c, r, t). Each thread scans NS=128
// samples sequentially (cumprod dependency); all loads coalesced across the
// contiguous 64-wide (r,t) group.
//
// OutMode: 0 -> write real part only (out_size == N_ELEMS floats; harness
//               converted complex64 via astype -> real part)
//          1 -> planar: re block then im block (out_size == 2*N_ELEMS floats)
__global__ void __launch_bounds__(256, 4) renderer_kernel(
    const float* __restrict__ x,
    const float* __restrict__ z_vals,
    const float* __restrict__ fc_vec,
    float* __restrict__ out,
    int out_mode)
{
    const int gid = blockIdx.x * blockDim.x + threadIdx.x;
    const int rt  = gid & (RT - 1);
    const int c   = (gid >> 6) % NC;
    const int ray = gid / (NC * RT);

    const float C_LIGHT = 299792458.0f;
    const float PI_F    = 3.14159265358979f;

    const float fc = __ldg(&fc_vec[NC + c]);                 // fc_down
    // Same op order as reference: ((2*pi)*fc)*1e9 / c
    const float wavenumber = 2.0f * PI_F * fc * 1.0e9f / C_LIGHT;
    const float ampk       = C_LIGHT / (fc * 1.0e9f * 4.0f * PI_F);

    const float* xb = x      + (size_t)ray * ((size_t)NS * X_S_STRIDE) + c * RT + rt;
    const float* zb = z_vals + (size_t)ray * ((size_t)NS * Z_S_STRIDE) + c * RT + rt;

    // Cody–Waite 2*pi split for range reduction of theta (|theta| <= ~1140)
    const float INV_2PI   = 0.15915494309189535f;
    const float TWO_PI_HI = 6.28318548202514648f;   // float(2*pi)
    const float TWO_PI_LO = -1.7484555e-7f;         // 2*pi - TWO_PI_HI

    float z_cur = __ldg(zb);            // z[0]
    float Tre = 1.0f, Tim = 0.0f;       // running product of factors 0..s-1
    float acc_re = 0.0f, acc_im = 0.0f;

    #pragma unroll 4
    for (int s = 0; s < NS; ++s) {
        const int xo = s * X_S_STRIDE;
        const float x_re  = __ldg(xb + xo);
        const float x_im  = __ldg(xb + xo + NC * RT);
        const float a_raw = __ldg(xb + xo + 2 * NC * RT);

        float z_next, dist;
        if (s < NS - 1) {
            z_next = __ldg(zb + (s + 1) * Z_S_STRIDE);
            dist   = z_next - z_cur;
        } else {
            z_next = z_cur;
            dist   = 1e-10f;
        }

        const float oma   = __expf(-a_raw);       // (1 - alpha)
        const float alpha = 1.0f - oma;
        const float amp   = __fdividef(ampk, z_cur);

        // contribution: ch * amp * (alpha * T_exclusive); T_exclusive(0) = 0
        if (s > 0) {
            const float g = amp * alpha;
            acc_re = fmaf(g, x_re * Tre - x_im * Tim, acc_re);
            acc_im = fmaf(g, x_re * Tim + x_im * Tre, acc_im);
        }

        // factor f = (1-alpha) * exp(-i*theta) + 1e-10  (epsilon on real part)
        const float theta = wavenumber * dist;    // f32, matching reference rounding
        const float n = rintf(theta * INV_2PI);
        float r = fmaf(-n, TWO_PI_HI, theta);
        r       = fmaf(-n, TWO_PI_LO, r);
        float sn, cs;
        __sincosf(r, &sn, &cs);                   // |r| <= pi: accurate fast path

        const float fre = fmaf(oma, cs, 1e-10f);
        const float fim = -oma * sn;

        const float nTre = Tre * fre - Tim * fim;
        const float nTim = Tre * fim + Tim * fre;
        Tre = nTre;
        Tim = nTim;
        z_cur = z_next;
    }

    if (out_mode == 0) {
        out[gid] = acc_re;                        // real part only
    } else {
        out[gid]           = acc_re;              // planar: re block, then im block
        out[gid + N_ELEMS] = acc_im;
    }
}

extern "C" void kernel_launch(void* const* d_in, const int* in_sizes, int n_in,
                              void* d_out, int out_size)
{
    // Dispatch inputs by element count — robust to metadata ordering.
    const float* x      = nullptr;
    const float* z_vals = nullptr;
    const float* fc_vec = nullptr;
    const long long X_N  = (long long)NRAYS * NS * 3 * NC * RT;  // 81,788,928
    const long long Z_N  = (long long)NRAYS * NS * 2 * NC * RT;  // 54,525,952
    const long long FC_N = 2 * NC;                               // 104
    for (int i = 0; i < n_in; ++i) {
        const long long n = (long long)in_sizes[i];
        if      (n == X_N)  x      = (const float*)d_in[i];
        else if (n == Z_N)  z_vals = (const float*)d_in[i];
        else if (n == FC_N) fc_vec = (const float*)d_in[i];
    }
    if (!x && n_in >= 1)      x      = (const float*)d_in[0];
    if (!z_vals && n_in >= 2) z_vals = (const float*)d_in[1];
    if (!fc_vec && n_in >= 3) fc_vec = (const float*)d_in[2];

    // Output representation by size:
    //   N_ELEMS      (212,992) -> float32 real part only (complex->astype(f32))
    //   2*N_ELEMS    (425,984) -> planar [re block | im block]
    //   (interleaved complex64 already refuted experimentally in R1-R3)
    const int out_mode = (out_size == N_ELEMS) ? 0 : 1;

    const int block = 256;
    const int grid  = N_ELEMS / block;              // 832
    renderer_kernel<<<grid, block>>>(x, z_vals, fc_vec, (float*)d_out, out_mode);
}

// round 6
// speedup vs baseline: 1.0419x; 1.0419x over previous
#include <cuda_runtime.h>

// Problem constants
#define NC 52
#define NR 4
#define NT 16
#define NS 128
#define NRAYS 64
#define RT (NR*NT)                 // 64 contiguous (r,t) per (ray,s,ch)
#define X_S_STRIDE (3*NC*RT)       // 9984 floats per s-step in x
#define Z_S_STRIDE (2*NC*RT)       // 6656 floats per s-step in z_vals
#define N_ELEMS (NRAYS*NC*RT)      // 212,992 complex outputs
#define NPAIR (N_ELEMS/2)          // 106,496 threads, 2 rt-channels each

// One thread per PAIR of adjacent (r,t) channels: float2 loads throughout,
// two independent 128-step complex scans per thread (2x ILP + 2x MLP).
// 416 blocks of 256 -> single wave at occ>=3 blocks/SM (no tail wave).
__global__ void __launch_bounds__(256, 4) renderer_kernel(
    const float* __restrict__ x,
    const float* __restrict__ z_vals,
    const float* __restrict__ fc_vec,
    float* __restrict__ out,
    int out_mode)
{
    const int gid = blockIdx.x * blockDim.x + threadIdx.x;
    const int pr  = gid & (RT/2 - 1);          // pair index within rt group (0..31)
    const int c   = (gid >> 5) % NC;
    const int ray = gid / (NC * (RT/2));

    const float C_LIGHT = 299792458.0f;
    const float PI_F    = 3.14159265358979f;

    const float fc = __ldg(&fc_vec[NC + c]);                 // fc_down
    const float wavenumber = 2.0f * PI_F * fc * 1.0e9f / C_LIGHT;
    const float ampk       = C_LIGHT / (fc * 1.0e9f * 4.0f * PI_F);

    const size_t base_off = (size_t)c * RT + (size_t)pr * 2;
    const float2* xb = (const float2*)(x      + (size_t)ray * ((size_t)NS * X_S_STRIDE) + base_off);
    const float2* zb = (const float2*)(z_vals + (size_t)ray * ((size_t)NS * Z_S_STRIDE) + base_off);
    // strides in float2 units
    const int XS2 = X_S_STRIDE / 2;            // 4992
    const int ZS2 = Z_S_STRIDE / 2;            // 3328
    const int NCRT2 = NC * RT / 2;             // 1664

    // Cody–Waite 2*pi split for range reduction of theta (|theta| <= ~1140)
    const float INV_2PI   = 0.15915494309189535f;
    const float TWO_PI_HI = 6.28318548202514648f;   // float(2*pi)
    const float TWO_PI_LO = -1.7484555e-7f;         // 2*pi - TWO_PI_HI

    float2 z_cur = __ldg(zb);                  // z[0] pair
    float Tre0 = 1.0f, Tim0 = 0.0f, Tre1 = 1.0f, Tim1 = 0.0f;
    float ar0 = 0.0f, ai0 = 0.0f, ar1 = 0.0f, ai1 = 0.0f;

    #pragma unroll 4
    for (int s = 0; s < NS; ++s) {
        const int xo = s * XS2;
        const float2 xre = __ldg(xb + xo);
        const float2 xim = __ldg(xb + xo + NCRT2);
        const float2 arw = __ldg(xb + xo + 2 * NCRT2);

        float2 z_next, dist;
        if (s < NS - 1) {
            z_next = __ldg(zb + (s + 1) * ZS2);
            dist.x = z_next.x - z_cur.x;
            dist.y = z_next.y - z_cur.y;
        } else {
            z_next = z_cur;
            dist.x = 1e-10f;
            dist.y = 1e-10f;
        }

        const float oma0 = __expf(-arw.x);     // (1 - alpha)
        const float oma1 = __expf(-arw.y);
        const float al0  = 1.0f - oma0;
        const float al1  = 1.0f - oma1;
        const float amp0 = __fdividef(ampk, z_cur.x);
        const float amp1 = __fdividef(ampk, z_cur.y);

        // contribution: ch * amp * (alpha * T_exclusive); T_exclusive(0) = 0
        if (s > 0) {
            const float g0 = amp0 * al0;
            const float g1 = amp1 * al1;
            ar0 = fmaf(g0, xre.x * Tre0 - xim.x * Tim0, ar0);
            ai0 = fmaf(g0, xre.x * Tim0 + xim.x * Tre0, ai0);
            ar1 = fmaf(g1, xre.y * Tre1 - xim.y * Tim1, ar1);
            ai1 = fmaf(g1, xre.y * Tim1 + xim.y * Tre1, ai1);
        }

        // factor f = (1-alpha) * exp(-i*theta) + 1e-10 (epsilon on real part)
        const float th0 = wavenumber * dist.x;
        const float th1 = wavenumber * dist.y;
        const float n0 = rintf(th0 * INV_2PI);
        const float n1 = rintf(th1 * INV_2PI);
        float r0 = fmaf(-n0, TWO_PI_HI, th0); r0 = fmaf(-n0, TWO_PI_LO, r0);
        float r1 = fmaf(-n1, TWO_PI_HI, th1); r1 = fmaf(-n1, TWO_PI_LO, r1);
        float sn0, cs0, sn1, cs1;
        __sincosf(r0, &sn0, &cs0);
        __sincosf(r1, &sn1, &cs1);

        const float fre0 = fmaf(oma0, cs0, 1e-10f);
        const float fim0 = -oma0 * sn0;
        const float fre1 = fmaf(oma1, cs1, 1e-10f);
        const float fim1 = -oma1 * sn1;

        const float nTre0 = Tre0 * fre0 - Tim0 * fim0;
        const float nTim0 = Tre0 * fim0 + Tim0 * fre0;
        const float nTre1 = Tre1 * fre1 - Tim1 * fim1;
        const float nTim1 = Tre1 * fim1 + Tim1 * fre1;
        Tre0 = nTre0; Tim0 = nTim0;
        Tre1 = nTre1; Tim1 = nTim1;
        z_cur = z_next;
    }

    if (out_mode == 0) {
        ((float2*)out)[gid] = make_float2(ar0, ar1);           // real part only
    } else {
        // planar: re block then im block; pair is contiguous in both
        ((float2*)(out))[gid]                 = make_float2(ar0, ar1);
        ((float2*)(out + N_ELEMS))[gid]       = make_float2(ai0, ai1);
    }
}

extern "C" void kernel_launch(void* const* d_in, const int* in_sizes, int n_in,
                              void* d_out, int out_size)
{
    // Dispatch inputs by element count — robust to metadata ordering.
    const float* x      = nullptr;
    const float* z_vals = nullptr;
    const float* fc_vec = nullptr;
    const long long X_N  = (long long)NRAYS * NS * 3 * NC * RT;  // 81,788,928
    const long long Z_N  = (long long)NRAYS * NS * 2 * NC * RT;  // 54,525,952
    const long long FC_N = 2 * NC;                               // 104
    for (int i = 0; i < n_in; ++i) {
        const long long n = (long long)in_sizes[i];
        if      (n == X_N)  x      = (const float*)d_in[i];
        else if (n == Z_N)  z_vals = (const float*)d_in[i];
        else if (n == FC_N) fc_vec = (const float*)d_in[i];
    }
    if (!x && n_in >= 1)      x      = (const float*)d_in[0];
    if (!z_vals && n_in >= 2) z_vals = (const float*)d_in[1];
    if (!fc_vec && n_in >= 3) fc_vec = (const float*)d_in[2];

    // Output: N_ELEMS floats -> real-only; 2*N_ELEMS -> planar [re | im]
    const int out_mode = (out_size == N_ELEMS) ? 0 : 1;

    const int block = 256;
    const int grid  = NPAIR / block;                // 416 blocks, single wave
    renderer_kernel<<<grid, block>>>(x, z_vals, fc_vec, (float*)d_out, out_mode);
}

// round 8
// speedup vs baseline: 1.2804x; 1.2289x over previous
#include <cuda_runtime.h>

// Problem constants
#define NC 52
#define NR 4
#define NT 16
#define NS 128
#define NRAYS 64
#define RT (NR*NT)                 // 64 contiguous (r,t) per (ray,s,ch)
#define X_S_STRIDE (3*NC*RT)       // 9984 floats per s-step in x
#define Z_S_STRIDE (2*NC*RT)       // 6656 floats per s-step in z_vals
#define N_ELEMS (NRAYS*NC*RT)      // 212,992 complex outputs

// Scalar mapping: one thread per output channel -> 212,992 threads = 45
// warps/SM (2x the pair version). Block=128, grid=1664; launch_bounds(128,12)
// caps regs at 42 so ceil(1664/148)=12 blocks fit residently => single wave,
// ZERO tail. s=0 and s=127 peeled: no per-iter branches, and the s=127 phase
// factor (never consumed by the exclusive cumprod) is skipped entirely.
__global__ void __launch_bounds__(128, 12) renderer_kernel(
    const float* __restrict__ x,
    const float* __restrict__ z_vals,
    const float* __restrict__ fc_vec,
    float* __restrict__ out,
    int out_mode)
{
    const int gid = blockIdx.x * blockDim.x + threadIdx.x;
    const int rt  = gid & (RT - 1);
    const int c   = (gid >> 6) % NC;
    const int ray = gid / (NC * RT);

    const float C_LIGHT = 299792458.0f;
    const float PI_F    = 3.14159265358979f;

    const float fc = __ldg(&fc_vec[NC + c]);                 // fc_down
    const float wavenumber = 2.0f * PI_F * fc * 1.0e9f / C_LIGHT;
    const float ampk       = C_LIGHT / (fc * 1.0e9f * 4.0f * PI_F);

    const float* xb = x      + (size_t)ray * ((size_t)NS * X_S_STRIDE) + c * RT + rt;
    const float* zb = z_vals + (size_t)ray * ((size_t)NS * Z_S_STRIDE) + c * RT + rt;

    // Cody–Waite 2*pi split for range reduction of theta (|theta| <= ~1140)
    const float INV_2PI   = 0.15915494309189535f;
    const float TWO_PI_HI = 6.28318548202514648f;   // float(2*pi)
    const float TWO_PI_LO = -1.7484555e-7f;         // 2*pi - TWO_PI_HI

    float Tre, Tim;                    // running product of factors 0..s-1
    float acc_re = 0.0f, acc_im = 0.0f;
    float z_cur;

    // ---- s = 0 (peeled): contribution is zero; only the factor matters.
    {
        const float z0 = __ldg(zb);
        const float z1 = __ldg(zb + Z_S_STRIDE);
        const float a_raw = __ldg(xb + 2 * NC * RT);
        const float dist  = z1 - z0;

        const float oma = __expf(-a_raw);
        const float theta = wavenumber * dist;
        const float n = rintf(theta * INV_2PI);
        float r = fmaf(-n, TWO_PI_HI, theta);
        r       = fmaf(-n, TWO_PI_LO, r);
        float sn, cs;
        __sincosf(r, &sn, &cs);
        Tre = fmaf(oma, cs, 1e-10f);
        Tim = -oma * sn;
        z_cur = z1;
    }

    // ---- s = 1 .. 126: uniform body, no branches.
    #pragma unroll 2
    for (int s = 1; s < NS - 1; ++s) {
        const int xo = s * X_S_STRIDE;
        const float x_re  = __ldg(xb + xo);
        const float x_im  = __ldg(xb + xo + NC * RT);
        const float a_raw = __ldg(xb + xo + 2 * NC * RT);
        const float z_next = __ldg(zb + (s + 1) * Z_S_STRIDE);
        const float dist = z_next - z_cur;

        const float oma   = __expf(-a_raw);     // (1 - alpha)
        const float amp   = __fdividef(ampk, z_cur);
        const float g     = amp * (1.0f - oma); // amp * alpha

        acc_re = fmaf(g, x_re * Tre - x_im * Tim, acc_re);
        acc_im = fmaf(g, x_re * Tim + x_im * Tre, acc_im);

        // factor f = (1-alpha)*exp(-i*theta) + 1e-10 (epsilon on real part)
        const float theta = wavenumber * dist;
        const float n = rintf(theta * INV_2PI);
        float r = fmaf(-n, TWO_PI_HI, theta);
        r       = fmaf(-n, TWO_PI_LO, r);
        float sn, cs;
        __sincosf(r, &sn, &cs);

        const float fre = fmaf(oma, cs, 1e-10f);
        const float fim = -oma * sn;

        const float nTre = Tre * fre - Tim * fim;
        const float nTim = Tre * fim + Tim * fre;
        Tre = nTre;
        Tim = nTim;
        z_cur = z_next;
    }

    // ---- s = 127 (peeled): contribution only; its factor is never consumed.
    {
        const int xo = (NS - 1) * X_S_STRIDE;
        const float x_re  = __ldg(xb + xo);
        const float x_im  = __ldg(xb + xo + NC * RT);
        const float a_raw = __ldg(xb + xo + 2 * NC * RT);

        const float oma = __expf(-a_raw);
        const float amp = __fdividef(ampk, z_cur);
        const float g   = amp * (1.0f - oma);

        acc_re = fmaf(g, x_re * Tre - x_im * Tim, acc_re);
        acc_im = fmaf(g, x_re * Tim + x_im * Tre, acc_im);
    }

    if (out_mode == 0) {
        out[gid] = acc_re;                      // real part only
    } else {
        out[gid]           = acc_re;            // planar: re block | im block
        out[gid + N_ELEMS] = acc_im;
    }
}

extern "C" void kernel_launch(void* const* d_in, const int* in_sizes, int n_in,
                              void* d_out, int out_size)
{
    // Dispatch inputs by element count — robust to metadata ordering.
    const float* x      = nullptr;
    const float* z_vals = nullptr;
    const float* fc_vec = nullptr;
    const long long X_N  = (long long)NRAYS * NS * 3 * NC * RT;  // 81,788,928
    const long long Z_N  = (long long)NRAYS * NS * 2 * NC * RT;  // 54,525,952
    const long long FC_N = 2 * NC;                               // 104
    for (int i = 0; i < n_in; ++i) {
        const long long n = (long long)in_sizes[i];
        if      (n == X_N)  x      = (const float*)d_in[i];
        else if (n == Z_N)  z_vals = (const float*)d_in[i];
        else if (n == FC_N) fc_vec = (const float*)d_in[i];
    }
    if (!x && n_in >= 1)      x      = (const float*)d_in[0];
    if (!z_vals && n_in >= 2) z_vals = (const float*)d_in[1];
    if (!fc_vec && n_in >= 3) fc_vec = (const float*)d_in[2];

    // Output: N_ELEMS floats -> real-only; 2*N_ELEMS -> planar [re | im]
    const int out_mode = (out_size == N_ELEMS) ? 0 : 1;

    const int block = 128;
    const int grid  = N_ELEMS / block;              // 1664 blocks, single wave
    renderer_kernel<<<grid, block>>>(x, z_vals, fc_vec, (float*)d_out, out_mode);
}

// round 9
// speedup vs baseline: 1.3076x; 1.0212x over previous
#include <cuda_runtime.h>

// Problem constants
#define NC 52
#define NR 4
#define NT 16
#define NS 128
#define NRAYS 64
#define RT (NR*NT)                 // 64 contiguous (r,t) per (ray,s,ch)
#define X_S_STRIDE (3*NC*RT)       // 9984 floats per s-step in x
#define Z_S_STRIDE (2*NC*RT)       // 6656 floats per s-step in z_vals
#define N_ELEMS (NRAYS*NC*RT)      // 212,992 complex outputs

// Scalar mapping, single wave (1664 blocks of 128, <=42 regs for 12-block
// residency). This round: explicit 1-iteration software pipeline — all 4
// loads for iter s+1 issue BEFORE iter s's compute, so each load is covered
// by a full iteration of FMA/MUFU work instead of stalling at its consumer.
__global__ void __launch_bounds__(128, 12) renderer_kernel(
    const float* __restrict__ x,
    const float* __restrict__ z_vals,
    const float* __restrict__ fc_vec,
    float* __restrict__ out,
    int out_mode)
{
    const int gid = blockIdx.x * blockDim.x + threadIdx.x;
    const int rt  = gid & (RT - 1);
    const int c   = (gid >> 6) % NC;
    const int ray = gid / (NC * RT);

    const float C_LIGHT = 299792458.0f;
    const float PI_F    = 3.14159265358979f;

    const float fc = __ldg(&fc_vec[NC + c]);                 // fc_down
    const float wavenumber = 2.0f * PI_F * fc * 1.0e9f / C_LIGHT;
    const float ampk       = C_LIGHT / (fc * 1.0e9f * 4.0f * PI_F);

    const float* xb = x      + (size_t)ray * ((size_t)NS * X_S_STRIDE) + c * RT + rt;
    const float* zb = z_vals + (size_t)ray * ((size_t)NS * Z_S_STRIDE) + c * RT + rt;

    // Cody–Waite 2*pi split for range reduction of theta (|theta| <= ~1140)
    const float INV_2PI   = 0.15915494309189535f;
    const float TWO_PI_HI = 6.28318548202514648f;   // float(2*pi)
    const float TWO_PI_LO = -1.7484555e-7f;         // 2*pi - TWO_PI_HI

    float Tre, Tim;                    // running product of factors 0..s-1
    float acc_re = 0.0f, acc_im = 0.0f;
    float z_cur;

    // ---- s = 0 (peeled): contribution is zero; only the factor matters.
    {
        const float z0    = __ldg(zb);
        const float z1    = __ldg(zb + Z_S_STRIDE);
        const float a_raw = __ldg(xb + 2 * NC * RT);
        const float dist  = z1 - z0;

        const float oma = __expf(-a_raw);
        const float theta = wavenumber * dist;
        const float n = rintf(theta * INV_2PI);
        float r = fmaf(-n, TWO_PI_HI, theta);
        r       = fmaf(-n, TWO_PI_LO, r);
        float sn, cs;
        __sincosf(r, &sn, &cs);
        Tre = fmaf(oma, cs, 1e-10f);
        Tim = -oma * sn;
        z_cur = z1;
    }

    // Prefetch registers for iteration s: loaded during iteration s-1.
    float p_xre  = __ldg(xb + X_S_STRIDE);
    float p_xim  = __ldg(xb + X_S_STRIDE + NC * RT);
    float p_araw = __ldg(xb + X_S_STRIDE + 2 * NC * RT);
    float p_znxt = __ldg(zb + 2 * Z_S_STRIDE);        // z[s+1] for s=1

    // ---- s = 1 .. 125: steady state with full 1-iter-ahead prefetch.
    #pragma unroll 2
    for (int s = 1; s <= 125; ++s) {
        // consume prefetched
        const float x_re   = p_xre;
        const float x_im   = p_xim;
        const float a_raw  = p_araw;
        const float z_next = p_znxt;

        // issue next iteration's loads FIRST (covered by this iter's compute)
        const int xo1 = (s + 1) * X_S_STRIDE;
        p_xre  = __ldg(xb + xo1);
        p_xim  = __ldg(xb + xo1 + NC * RT);
        p_araw = __ldg(xb + xo1 + 2 * NC * RT);
        p_znxt = __ldg(zb + (s + 2) * Z_S_STRIDE);    // max index 127: in bounds

        const float dist = z_next - z_cur;
        const float oma  = __expf(-a_raw);            // (1 - alpha)
        const float amp  = __fdividef(ampk, z_cur);
        const float g    = amp * (1.0f - oma);        // amp * alpha

        acc_re = fmaf(g, x_re * Tre - x_im * Tim, acc_re);
        acc_im = fmaf(g, x_re * Tim + x_im * Tre, acc_im);

        // factor f = (1-alpha)*exp(-i*theta) + 1e-10 (epsilon on real part)
        const float theta = wavenumber * dist;
        const float n = rintf(theta * INV_2PI);
        float r = fmaf(-n, TWO_PI_HI, theta);
        r       = fmaf(-n, TWO_PI_LO, r);
        float sn, cs;
        __sincosf(r, &sn, &cs);

        const float fre = fmaf(oma, cs, 1e-10f);
        const float fim = -oma * sn;

        const float nTre = Tre * fre - Tim * fim;
        const float nTim = Tre * fim + Tim * fre;
        Tre = nTre;
        Tim = nTim;
        z_cur = z_next;
    }

    // ---- s = 126: consume prefetched (x@126, z@127); prefetch x@127 only.
    {
        const float x_re   = p_xre;
        const float x_im   = p_xim;
        const float a_raw  = p_araw;
        const float z_next = p_znxt;                  // z[127]

        const int xo1 = 127 * X_S_STRIDE;
        p_xre  = __ldg(xb + xo1);
        p_xim  = __ldg(xb + xo1 + NC * RT);
        p_araw = __ldg(xb + xo1 + 2 * NC * RT);

        const float dist = z_next - z_cur;
        const float oma  = __expf(-a_raw);
        const float amp  = __fdividef(ampk, z_cur);
        const float g    = amp * (1.0f - oma);

        acc_re = fmaf(g, x_re * Tre - x_im * Tim, acc_re);
        acc_im = fmaf(g, x_re * Tim + x_im * Tre, acc_im);

        const float theta = wavenumber * dist;
        const float n = rintf(theta * INV_2PI);
        float r = fmaf(-n, TWO_PI_HI, theta);
        r       = fmaf(-n, TWO_PI_LO, r);
        float sn, cs;
        __sincosf(r, &sn, &cs);

        const float fre = fmaf(oma, cs, 1e-10f);
        const float fim = -oma * sn;

        const float nTre = Tre * fre - Tim * fim;
        const float nTim = Tre * fim + Tim * fre;
        Tre = nTre;
        Tim = nTim;
        z_cur = z_next;
    }

    // ---- s = 127 (peeled): contribution only; its factor is never consumed.
    {
        const float oma = __expf(-p_araw);
        const float amp = __fdividef(ampk, z_cur);
        const float g   = amp * (1.0f - oma);

        acc_re = fmaf(g, p_xre * Tre - p_xim * Tim, acc_re);
        acc_im = fmaf(g, p_xre * Tim + p_xim * Tre, acc_im);
    }

    if (out_mode == 0) {
        out[gid] = acc_re;                      // real part only
    } else {
        out[gid]           = acc_re;            // planar: re block | im block
        out[gid + N_ELEMS] = acc_im;
    }
}

extern "C" void kernel_launch(void* const* d_in, const int* in_sizes, int n_in,
                              void* d_out, int out_size)
{
    // Dispatch inputs by element count — robust to metadata ordering.
    const float* x      = nullptr;
    const float* z_vals = nullptr;
    const float* fc_vec = nullptr;
    const long long X_N  = (long long)NRAYS * NS * 3 * NC * RT;  // 81,788,928
    const long long Z_N  = (long long)NRAYS * NS * 2 * NC * RT;  // 54,525,952
    const long long FC_N = 2 * NC;                               // 104
    for (int i = 0; i < n_in; ++i) {
        const long long n = (long long)in_sizes[i];
        if      (n == X_N)  x      = (const float*)d_in[i];
        else if (n == Z_N)  z_vals = (const float*)d_in[i];
        else if (n == FC_N) fc_vec = (const float*)d_in[i];
    }
    if (!x && n_in >= 1)      x      = (const float*)d_in[0];
    if (!z_vals && n_in >= 2) z_vals = (const float*)d_in[1];
    if (!fc_vec && n_in >= 3) fc_vec = (const float*)d_in[2];

    // Output: N_ELEMS floats -> real-only; 2*N_ELEMS -> planar [re | im]
    const int out_mode = (out_size == N_ELEMS) ? 0 : 1;

    const int block = 128;
    const int grid  = N_ELEMS / block;              // 1664 blocks, single wave
    renderer_kernel<<<grid, block>>>(x, z_vals, fc_vec, (float*)d_out, out_mode);
}

// round 10
// speedup vs baseline: 1.3116x; 1.0031x over previous
#include <cuda_runtime.h>

// Problem constants
#define NC 52
#define NR 4
#define NT 16
#define NS 128
#define NRAYS 64
#define RT (NR*NT)                 // 64 contiguous (r,t) per (ray,s,ch)
#define X_S_STRIDE (3*NC*RT)       // 9984 floats per s-step in x
#define Z_S_STRIDE (2*NC*RT)       // 6656 floats per s-step in z_vals
#define N_ELEMS (NRAYS*NC*RT)      // 212,992 complex outputs

// Factorized recurrence: since (1-alpha) = exp(-a_raw) exactly,
//   T_<s = (prod_j exp(-a_j)) * exp(-i * sum_j theta_j)   (epsilon ~1e-10
// dropped: relative effect <= 4e-6). Magnitude is a running scalar product E,
// phase is a wrapped accumulator phi (|phi|<=~13 => 5e-7/step rounding).
// This removes the complex-multiply carried chain and frees registers, which
// are spent on TWO-iteration-ahead prefetch (8 outstanding loads/thread) to
// raise bytes-in-flight against the DRAM latency/bandwidth equilibrium.
__global__ void __launch_bounds__(128, 12) renderer_kernel(
    const float* __restrict__ x,
    const float* __restrict__ z_vals,
    const float* __restrict__ fc_vec,
    float* __restrict__ out,
    int out_mode)
{
    const int gid = blockIdx.x * blockDim.x + threadIdx.x;
    const int rt  = gid & (RT - 1);
    const int c   = (gid >> 6) % NC;
    const int ray = gid / (NC * RT);

    const float C_LIGHT = 299792458.0f;
    const float PI_F    = 3.14159265358979f;

    const float fc = __ldg(&fc_vec[NC + c]);                 // fc_down
    const float wavenumber = 2.0f * PI_F * fc * 1.0e9f / C_LIGHT;
    const float ampk       = C_LIGHT / (fc * 1.0e9f * 4.0f * PI_F);

    const float* xb = x      + (size_t)ray * ((size_t)NS * X_S_STRIDE) + c * RT + rt;
    const float* zb = z_vals + (size_t)ray * ((size_t)NS * Z_S_STRIDE) + c * RT + rt;

    const float INV_2PI   = 0.15915494309189535f;
    const float TWO_PI_HI = 6.28318548202514648f;   // float(2*pi)
    const float TWO_PI_LO = -1.7484555e-7f;         // 2*pi - TWO_PI_HI

    float E;                          // prod exp(-a_j), j < s
    float phi;                        // wrapped sum theta_j, j < s
    float acc_re = 0.0f, acc_im = 0.0f;
    float z_cur;

    // ---- s = 0 (peeled): contribution is zero; seed E and phi.
    {
        const float z0 = __ldg(zb);
        const float z1 = __ldg(zb + Z_S_STRIDE);
        const float a0 = __ldg(xb + 2 * NC * RT);
        E = __expf(-a0);
        const float th = wavenumber * (z1 - z0);
        const float n = rintf(th * INV_2PI);
        phi = fmaf(-n, TWO_PI_HI, th);
        phi = fmaf(-n, TWO_PI_LO, phi);
        z_cur = z1;
    }

    // Two rotating prefetch sets; set b holds {x3[t], z[t+1]} for iteration t.
    float px[2], pxi[2], pa[2], pz[2];
    {
        const int xo1 = 1 * X_S_STRIDE, xo2 = 2 * X_S_STRIDE;
        px[0]  = __ldg(xb + xo1);
        pxi[0] = __ldg(xb + xo1 + NC * RT);
        pa[0]  = __ldg(xb + xo1 + 2 * NC * RT);
        pz[0]  = __ldg(zb + 2 * Z_S_STRIDE);
        px[1]  = __ldg(xb + xo2);
        pxi[1] = __ldg(xb + xo2 + NC * RT);
        pa[1]  = __ldg(xb + xo2 + 2 * NC * RT);
        pz[1]  = __ldg(zb + 3 * Z_S_STRIDE);
    }

    // ---- s = 1 .. 124: steady state, 2-ahead prefetch.
    #pragma unroll 2
    for (int s = 1; s <= 124; ++s) {
        const int b = (s - 1) & 1;
        const float x_re   = px[b];
        const float x_im   = pxi[b];
        const float a_raw  = pa[b];
        const float z_next = pz[b];

        // prefetch iteration s+2 into the freed set (z index s+3 <= 127)
        const int xo = (s + 2) * X_S_STRIDE;
        px[b]  = __ldg(xb + xo);
        pxi[b] = __ldg(xb + xo + NC * RT);
        pa[b]  = __ldg(xb + xo + 2 * NC * RT);
        pz[b]  = __ldg(zb + (s + 3) * Z_S_STRIDE);

        // contribution uses CURRENT (exclusive) E, phi
        float sn, cs;
        __sincosf(phi, &sn, &cs);                 // T phase = cs - i*sn
        const float e     = __expf(-a_raw);       // (1 - alpha)
        const float alpha = 1.0f - e;
        const float g     = __fdividef(ampk * E * alpha, z_cur);

        const float cre = fmaf(x_im, sn,  x_re * cs);
        const float cim = fmaf(x_im, cs, -x_re * sn);
        acc_re = fmaf(g, cre, acc_re);
        acc_im = fmaf(g, cim, acc_im);

        // advance magnitude and wrapped phase
        E *= e;
        const float th = wavenumber * (z_next - z_cur);
        float p = phi + th;
        const float n = rintf(p * INV_2PI);
        p   = fmaf(-n, TWO_PI_HI, p);
        phi = fmaf(-n, TWO_PI_LO, p);
        z_cur = z_next;
    }

    // ---- s = 125 (b=0): consume; prefetch x[127] only (its z is unused).
    {
        const float x_re = px[0], x_im = pxi[0], a_raw = pa[0], z_next = pz[0];
        const int xo = 127 * X_S_STRIDE;
        px[0]  = __ldg(xb + xo);
        pxi[0] = __ldg(xb + xo + NC * RT);
        pa[0]  = __ldg(xb + xo + 2 * NC * RT);

        float sn, cs;
        __sincosf(phi, &sn, &cs);
        const float e     = __expf(-a_raw);
        const float alpha = 1.0f - e;
        const float g     = __fdividef(ampk * E * alpha, z_cur);
        acc_re = fmaf(g, fmaf(x_im, sn,  x_re * cs), acc_re);
        acc_im = fmaf(g, fmaf(x_im, cs, -x_re * sn), acc_im);

        E *= e;
        const float th = wavenumber * (z_next - z_cur);
        float p = phi + th;
        const float n = rintf(p * INV_2PI);
        p   = fmaf(-n, TWO_PI_HI, p);
        phi = fmaf(-n, TWO_PI_LO, p);
        z_cur = z_next;
    }

    // ---- s = 126 (b=1): consume; no prefetch.
    {
        const float x_re = px[1], x_im = pxi[1], a_raw = pa[1], z_next = pz[1];

        float sn, cs;
        __sincosf(phi, &sn, &cs);
        const float e     = __expf(-a_raw);
        const float alpha = 1.0f - e;
        const float g     = __fdividef(ampk * E * alpha, z_cur);
        acc_re = fmaf(g, fmaf(x_im, sn,  x_re * cs), acc_re);
        acc_im = fmaf(g, fmaf(x_im, cs, -x_re * sn), acc_im);

        E *= e;
        const float th = wavenumber * (z_next - z_cur);
        float p = phi + th;
        const float n = rintf(p * INV_2PI);
        p   = fmaf(-n, TWO_PI_HI, p);
        phi = fmaf(-n, TWO_PI_LO, p);
        z_cur = z_next;
    }

    // ---- s = 127 (peeled): contribution only; its factor is never consumed.
    {
        const float x_re = px[0], x_im = pxi[0], a_raw = pa[0];
        float sn, cs;
        __sincosf(phi, &sn, &cs);
        const float e     = __expf(-a_raw);
        const float alpha = 1.0f - e;
        const float g     = __fdividef(ampk * E * alpha, z_cur);
        acc_re = fmaf(g, fmaf(x_im, sn,  x_re * cs), acc_re);
        acc_im = fmaf(g, fmaf(x_im, cs, -x_re * sn), acc_im);
    }

    if (out_mode == 0) {
        out[gid] = acc_re;                      // real part only
    } else {
        out[gid]           = acc_re;            // planar: re block | im block
        out[gid + N_ELEMS] = acc_im;
    }
}

extern "C" void kernel_launch(void* const* d_in, const int* in_sizes, int n_in,
                              void* d_out, int out_size)
{
    // Dispatch inputs by element count — robust to metadata ordering.
    const float* x      = nullptr;
    const float* z_vals = nullptr;
    const float* fc_vec = nullptr;
    const long long X_N  = (long long)NRAYS * NS * 3 * NC * RT;  // 81,788,928
    const long long Z_N  = (long long)NRAYS * NS * 2 * NC * RT;  // 54,525,952
    const long long FC_N = 2 * NC;                               // 104
    for (int i = 0; i < n_in; ++i) {
        const long long n = (long long)in_sizes[i];
        if      (n == X_N)  x      = (const float*)d_in[i];
        else if (n == Z_N)  z_vals = (const float*)d_in[i];
        else if (n == FC_N) fc_vec = (const float*)d_in[i];
    }
    if (!x && n_in >= 1)      x      = (const float*)d_in[0];
    if (!z_vals && n_in >= 2) z_vals = (const float*)d_in[1];
    if (!fc_vec && n_in >= 3) fc_vec = (const float*)d_in[2];

    // Output: N_ELEMS floats -> real-only; 2*N_ELEMS -> planar [re | im]
    const int out_mode = (out_size == N_ELEMS) ? 0 : 1;

    const int block = 128;
    const int grid  = N_ELEMS / block;              // 1664 blocks, single wave
    renderer_kernel<<<grid, block>>>(x, z_vals, fc_vec, (float*)d_out, out_mode);
}